// round 3
// baseline (speedup 1.0000x reference)
#include <cuda_runtime.h>
#include <math.h>

#define B_  2048
#define T_  512
#define F_  32
#define H_  128
#define G_  512
#define BT  14        // batch rows per CTA -> 147 CTAs, one wave on 148 SMs
#define P_  7         // batch pairs per CTA
#define NT  256
#define CROWS 224     // Whh0 slot-rows cached in SMEM (warps 0..6 of gate A)

typedef unsigned long long ull;

// Slot-permuted, gate-major weight rows (k contiguous). slot = q*256 + t;
// thread t owns slots t (q=0) and 256+t (q=1).
// gate(t,q) = (t&1)*128 + q*256 + (t>>1):
//   lane-even threads own (i_j, g_j), lane-odd own (f_j, o_j), j = t>>1.
__device__ float g_Wih0p[512 * 32];
__device__ float g_Whh0p[512 * 128];
__device__ float g_Wih1p[512 * 128];
__device__ float g_Whh1p[512 * 128];
__device__ float g_b0p[512];
__device__ float g_b1p[512];

__global__ void prep(const float* __restrict__ Wih0,
                     const float* __restrict__ Whh0,
                     const float* __restrict__ b0,
                     const float* __restrict__ Wih1,
                     const float* __restrict__ Whh1,
                     const float* __restrict__ b1) {
    int idx = blockIdx.x * blockDim.x + threadIdx.x;   // 0 .. 512*128-1
    int slot = idx >> 7, k = idx & 127;
    int t = slot & 255, q = slot >> 8;
    int gate = (t & 1) * 128 + q * 256 + (t >> 1);
    g_Whh0p[slot * 128 + k] = Whh0[gate * 128 + k];
    g_Wih1p[slot * 128 + k] = Wih1[gate * 128 + k];
    g_Whh1p[slot * 128 + k] = Whh1[gate * 128 + k];
    if (k < 32) g_Wih0p[slot * 32 + k] = Wih0[gate * 32 + k];
    if (k == 0) { g_b0p[slot] = b0[gate]; g_b1p[slot] = b1[gate]; }
}

__device__ __forceinline__ ull ffma2(ull a, ull b, ull c) {
    ull d;
    asm("fma.rn.f32x2 %0, %1, %2, %3;" : "=l"(d) : "l"(a), "l"(b), "l"(c));
    return d;
}
__device__ __forceinline__ ull dup2(float w) {
    ull d;
    asm("mov.b64 %0, {%1, %1};" : "=l"(d) : "f"(w));
    return d;
}
__device__ __forceinline__ float2 u2f(ull v) {
    float2 r;
    asm("mov.b64 {%0, %1}, %2;" : "=f"(r.x), "=f"(r.y) : "l"(v));
    return r;
}
__device__ __forceinline__ ull f2u(float2 v) {
    ull r;
    asm("mov.b64 %0, {%1, %2};" : "=l"(r) : "f"(v.x), "f"(v.y));
    return r;
}
__device__ __forceinline__ float sigm(float x) {
    return 1.0f / (1.0f + __expf(-x));
}
__device__ __forceinline__ float tanh_f(float x) {
    float e = __expf(-2.0f * fabsf(x));
    float t = (1.0f - e) / (1.0f + e);
    return x >= 0.0f ? t : -t;
}

// one k-group (4 k-values) for both of this thread's gates, all 7 pairs
template <int K>
__device__ __forceinline__ void kgroup(float4 wa, float4 wb,
                                       const float2* __restrict__ hp,
                                       ull z[2][P_], int kg) {
    ull a0 = dup2(wa.x), a1 = dup2(wa.y), a2 = dup2(wa.z), a3 = dup2(wa.w);
    ull b0 = dup2(wb.x), b1 = dup2(wb.y), b2 = dup2(wb.z), b3 = dup2(wb.w);
#pragma unroll
    for (int p = 0; p < P_; ++p) {
        const ulonglong2* hv = (const ulonglong2*)(hp + p * K) + 2 * kg;
        ulonglong2 v0 = hv[0];   // batch pairs for k=4kg, 4kg+1
        ulonglong2 v1 = hv[1];   // k=4kg+2, 4kg+3
        ull za = z[0][p], zb = z[1][p];
        za = ffma2(v0.x, a0, za);
        za = ffma2(v0.y, a1, za);
        za = ffma2(v1.x, a2, za);
        za = ffma2(v1.y, a3, za);
        zb = ffma2(v0.x, b0, zb);
        zb = ffma2(v0.y, b1, zb);
        zb = ffma2(v1.x, b2, zb);
        zb = ffma2(v1.y, b3, zb);
        z[0][p] = za; z[1][p] = zb;
    }
}

// GEMM panel: z[q][p] += hp[p][:] . row{A,B}[:]   (KG = K/4 k-groups)
// 4-deep rotating prefetch: value consumed 4 k-groups after its load.
template <int KG, int K>
__device__ __forceinline__ void panel(const float* __restrict__ rowA,
                                      const float* __restrict__ rowB,
                                      const float2* __restrict__ hp,
                                      ull z[2][P_]) {
    const float4* A4 = (const float4*)rowA;
    const float4* B4 = (const float4*)rowB;
    float4 a0 = A4[0], a1 = A4[1], a2 = A4[2], a3 = A4[3];
    float4 b0 = B4[0], b1 = B4[1], b2 = B4[2], b3 = B4[3];
    int kg = 0;
#pragma unroll 1
    for (; kg + 4 < KG; kg += 4) {
        kgroup<K>(a0, b0, hp, z, kg);     a0 = A4[kg + 4]; b0 = B4[kg + 4];
        kgroup<K>(a1, b1, hp, z, kg + 1); a1 = A4[kg + 5]; b1 = B4[kg + 5];
        kgroup<K>(a2, b2, hp, z, kg + 2); a2 = A4[kg + 6]; b2 = B4[kg + 6];
        kgroup<K>(a3, b3, hp, z, kg + 3); a3 = A4[kg + 7]; b3 = B4[kg + 7];
    }
    kgroup<K>(a0, b0, hp, z, kg);
    kgroup<K>(a1, b1, hp, z, kg + 1);
    kgroup<K>(a2, b2, hp, z, kg + 2);
    kgroup<K>(a3, b3, hp, z, kg + 3);
}

extern __shared__ float smem[];

__global__ void __launch_bounds__(NT, 1)
lstm_persistent(const float* __restrict__ x,
                const float* __restrict__ Wfc,
                const float* __restrict__ bfc,
                float* __restrict__ out) {
    // SMEM: [Wih0 cache 16384 f][Whh0 cache 28672 f][h0 x2][h1 x2][x x2]
    float* sWih0 = smem;                       // 512*32
    float* sWhh0 = smem + 512 * 32;            // CROWS*128
    float2* hbase = (float2*)(smem + 512 * 32 + CROWS * 128);
    float2* h0b[2] = { hbase,              hbase + P_ * H_ };
    float2* h1b[2] = { hbase + 2 * P_ * H_, hbase + 3 * P_ * H_ };
    float2* xb[2]  = { hbase + 4 * P_ * H_, hbase + 4 * P_ * H_ + P_ * F_ };

    const int tid = threadIdx.x;
    const int s = tid & 1;
    const int j = tid >> 1;
    const int b_base = blockIdx.x * BT;
    const int nb = min(BT, B_ - b_base);

    // fill weight caches
    for (int i = tid; i < 512 * 32; i += NT) sWih0[i] = g_Wih0p[i];
    for (int i = tid; i < CROWS * 128; i += NT) sWhh0[i] = g_Whh0p[i];
    // zero h buffers
    for (int i = tid; i < 4 * P_ * H_; i += NT) hbase[i] = make_float2(0.f, 0.f);
    // stage x(t=0) into xb[0]
    for (int i = tid; i < BT * F_; i += NT) {
        int b = i / F_, f = i % F_;
        float v = (b < nb) ? x[((size_t)(b_base + b) * T_) * F_ + f] : 0.0f;
        ((float*)xb[0])[(b >> 1) * (2 * F_) + f * 2 + (b & 1)] = v;
    }

    const ull bias0A = dup2(g_b0p[tid]);
    const ull bias0B = dup2(g_b0p[256 + tid]);
    const ull bias1A = dup2(g_b1p[tid]);
    const ull bias1B = dup2(g_b1p[256 + tid]);

    // row pointers: slot t (gate A) and slot 256+t (gate B)
    const float* wih0A = sWih0 + tid * 32;
    const float* wih0B = sWih0 + (256 + tid) * 32;
    const float* whh0A = (tid < CROWS) ? (sWhh0 + tid * 128)
                                       : (g_Whh0p + tid * 128);
    const float* whh0B = g_Whh0p + (256 + tid) * 128;
    const float* wih1A = g_Wih1p + tid * 128;
    const float* wih1B = g_Wih1p + (256 + tid) * 128;
    const float* whh1A = g_Whh1p + tid * 128;
    const float* whh1B = g_Whh1p + (256 + tid) * 128;

    ull c0[P_], c1[P_];
#pragma unroll
    for (int p = 0; p < P_; ++p) { c0[p] = 0ull; c1[p] = 0ull; }

    __syncthreads();

    int cur = 0;
    for (int t = 0; t < T_; ++t) {
        // ---- layer 0 GEMM (z in registers) ----
        ull z[2][P_];
#pragma unroll
        for (int p = 0; p < P_; ++p) { z[0][p] = bias0A; z[1][p] = bias0B; }
        panel<8, F_>(wih0A, wih0B, xb[cur], z);
        panel<32, H_>(whh0A, whh0B, h0b[cur], z);

        // ---- layer 0 gate update -> h0b[cur^1], c0 in regs ----
#pragma unroll
        for (int p = 0; p < P_; ++p) {
            float2 zA = u2f(z[0][p]);
            float2 zB = u2f(z[1][p]);
            float2 va, vo;
            if (s == 0) {   // i = sigm(zA), g = tanh(zB); send i*g
                va.x = sigm(zA.x) * tanh_f(zB.x);
                va.y = sigm(zA.y) * tanh_f(zB.y);
                vo = va;
            } else {        // f = sigm(zA), o = sigm(zB)
                va.x = sigm(zA.x); va.y = sigm(zA.y);
                vo.x = sigm(zB.x); vo.y = sigm(zB.y);
            }
            float rx = __shfl_xor_sync(0xffffffffu, va.x, 1);
            float ry = __shfl_xor_sync(0xffffffffu, va.y, 1);
            if (s == 1) {
                float2 cc = u2f(c0[p]);
                cc.x = va.x * cc.x + rx;
                cc.y = va.y * cc.y + ry;
                c0[p] = f2u(cc);
                float2 hh;
                hh.x = vo.x * tanh_f(cc.x);
                hh.y = vo.y * tanh_f(cc.y);
                h0b[cur ^ 1][p * H_ + j] = hh;
            }
        }

        // stage x(t+1) into xb[cur^1] (read next step, after next sync)
        if (t + 1 < T_) {
            for (int i = tid; i < BT * F_; i += NT) {
                int b = i / F_, f = i % F_;
                float v = (b < nb)
                    ? x[((size_t)(b_base + b) * T_ + (t + 1)) * F_ + f]
                    : 0.0f;
                ((float*)xb[cur ^ 1])[(b >> 1) * (2 * F_) + f * 2 + (b & 1)] = v;
            }
        }
        __syncthreads();

        // ---- layer 1 GEMM ----
#pragma unroll
        for (int p = 0; p < P_; ++p) { z[0][p] = bias1A; z[1][p] = bias1B; }
        panel<32, H_>(wih1A, wih1B, h0b[cur ^ 1], z);
        panel<32, H_>(whh1A, whh1B, h1b[cur], z);

        // ---- layer 1 gate update -> h1b[cur^1], c1 in regs ----
#pragma unroll
        for (int p = 0; p < P_; ++p) {
            float2 zA = u2f(z[0][p]);
            float2 zB = u2f(z[1][p]);
            float2 va, vo;
            if (s == 0) {
                va.x = sigm(zA.x) * tanh_f(zB.x);
                va.y = sigm(zA.y) * tanh_f(zB.y);
                vo = va;
            } else {
                va.x = sigm(zA.x); va.y = sigm(zA.y);
                vo.x = sigm(zB.x); vo.y = sigm(zB.y);
            }
            float rx = __shfl_xor_sync(0xffffffffu, va.x, 1);
            float ry = __shfl_xor_sync(0xffffffffu, va.y, 1);
            if (s == 1) {
                float2 cc = u2f(c1[p]);
                cc.x = va.x * cc.x + rx;
                cc.y = va.y * cc.y + ry;
                c1[p] = f2u(cc);
                float2 hh;
                hh.x = vo.x * tanh_f(cc.x);
                hh.y = vo.y * tanh_f(cc.y);
                h1b[cur ^ 1][p * H_ + j] = hh;
            }
        }
        __syncthreads();
        cur ^= 1;
    }

    // FC head: h1b[cur] holds h1(T-1)
    if (tid < nb) {
        const float2* hf = h1b[cur] + (tid >> 1) * H_;
        float acc = bfc[0];
        int sel = tid & 1;
#pragma unroll
        for (int k = 0; k < H_; ++k) {
            float2 v = hf[k];
            acc = fmaf(sel ? v.y : v.x, Wfc[k], acc);
        }
        out[b_base + tid] = acc;
    }
}

extern "C" void kernel_launch(void* const* d_in, const int* in_sizes, int n_in,
                              void* d_out, int out_size) {
    const float* x    = (const float*)d_in[0];
    const float* Wih0 = (const float*)d_in[1];
    const float* Whh0 = (const float*)d_in[2];
    const float* b0   = (const float*)d_in[3];
    const float* Wih1 = (const float*)d_in[4];
    const float* Whh1 = (const float*)d_in[5];
    const float* b1   = (const float*)d_in[6];
    const float* Wfc  = (const float*)d_in[7];
    const float* bfc  = (const float*)d_in[8];
    float* out = (float*)d_out;
    (void)in_sizes; (void)n_in; (void)out_size;

    prep<<<256, 256>>>(Wih0, Whh0, b0, Wih1, Whh1, b1);

    const int smem_bytes =
        (512 * 32 + CROWS * 128) * (int)sizeof(float) +
        (4 * P_ * H_ + 2 * P_ * F_) * (int)sizeof(float2);
    cudaFuncSetAttribute(lstm_persistent,
                         cudaFuncAttributeMaxDynamicSharedMemorySize,
                         smem_bytes);

    lstm_persistent<<<(B_ + BT - 1) / BT, NT, smem_bytes>>>(x, Wfc, bfc, out);
}

// round 4
// speedup vs baseline: 2.4617x; 2.4617x over previous
#include <cuda_runtime.h>
#include <math.h>

// Problem constants
#define B_  2048
#define T_  512
#define F_  32
#define H_  128
#define G_  512      // 4*H
#define BT  14       // batch rows per CTA -> 147 CTAs = one wave on 148 SMs
#define P_  7        // batch-row pairs per CTA
#define NT  256      // threads; each owns gates tid and tid+256
#define PST 9        // zbuf pair stride in ull (odd -> low-conflict)

typedef unsigned long long ull;

// Weights reorganized as [kg][gate] float4: one coalesced LDG.128 per gate per
// k-group gives that gate's 4 consecutive k-values. Padded +2 kg rows so the
// distance-2 prefetch can read unconditionally.
__device__ float4 g_Wih0T4[(F_ / 4 + 2) * G_];
__device__ float4 g_Whh0T4[(H_ / 4 + 2) * G_];
__device__ float4 g_Wih1T4[(H_ / 4 + 2) * G_];
__device__ float4 g_Whh1T4[(H_ / 4 + 2) * G_];

__global__ void prep(const float* __restrict__ Wih0,
                     const float* __restrict__ Whh0,
                     const float* __restrict__ Wih1,
                     const float* __restrict__ Whh1) {
    int idx = blockIdx.x * blockDim.x + threadIdx.x;  // 0 .. 512*32-1
    int g = idx >> 5, kg = idx & 31;
    if (kg < F_ / 4)
        g_Wih0T4[kg * G_ + g] = *(const float4*)(Wih0 + g * F_ + 4 * kg);
    g_Whh0T4[kg * G_ + g] = *(const float4*)(Whh0 + g * H_ + 4 * kg);
    g_Wih1T4[kg * G_ + g] = *(const float4*)(Wih1 + g * H_ + 4 * kg);
    g_Whh1T4[kg * G_ + g] = *(const float4*)(Whh1 + g * H_ + 4 * kg);
}

__device__ __forceinline__ ull ffma2(ull a, ull b, ull c) {
    ull d;
    asm("fma.rn.f32x2 %0, %1, %2, %3;" : "=l"(d) : "l"(a), "l"(b), "l"(c));
    return d;
}
__device__ __forceinline__ ull dup2(float w) {
    ull d;
    asm("mov.b64 %0, {%1, %1};" : "=l"(d) : "f"(w));
    return d;
}
__device__ __forceinline__ ull pack2(float lo, float hi) {
    return (ull)__float_as_uint(lo) | ((ull)__float_as_uint(hi) << 32);
}
__device__ __forceinline__ float sigm(float x) {
    return 1.0f / (1.0f + __expf(-x));
}
__device__ __forceinline__ float tanh_f(float x) {
    float e = __expf(-2.0f * fabsf(x));
    float t = (1.0f - e) / (1.0f + e);
    return x >= 0.0f ? t : -t;
}

// One K-panel: z[q][p] += sum_k hpair[p][k] * W[k][g_q], f32x2 packed.
// hp: pair-interleaved activations, P_ rows of KDIM float2.
// W4: [kg][gate] float4 scalar weights; distance-2 rolling prefetch.
template <int KDIM>
__device__ __forceinline__ void gemm2(const float4* __restrict__ W4,
                                      const float2* __restrict__ hp,
                                      ull z[2][P_], int g0) {
    constexpr int KG = KDIM / 4;
    const float4* pA = W4 + g0;
    const float4* pB = W4 + g0 + 256;
    float4 wa0 = pA[0], wa1 = pA[G_];
    float4 wb0 = pB[0], wb1 = pB[G_];
#pragma unroll 1
    for (int kg = 0; kg < KG; ++kg) {
        float4 na = pA[(size_t)(kg + 2) * G_];
        float4 nb = pB[(size_t)(kg + 2) * G_];
        ull a0 = dup2(wa0.x), a1 = dup2(wa0.y), a2 = dup2(wa0.z), a3 = dup2(wa0.w);
        ull b0 = dup2(wb0.x), b1 = dup2(wb0.y), b2 = dup2(wb0.z), b3 = dup2(wb0.w);
#pragma unroll
        for (int p = 0; p < P_; ++p) {
            const ulonglong2* hv = (const ulonglong2*)(hp + p * KDIM);
            ulonglong2 v0 = hv[2 * kg];      // batch pairs for k=4kg, 4kg+1
            ulonglong2 v1 = hv[2 * kg + 1];  // k=4kg+2, 4kg+3
            ull z0 = z[0][p], z1 = z[1][p];
            z0 = ffma2(v0.x, a0, z0);
            z0 = ffma2(v0.y, a1, z0);
            z0 = ffma2(v1.x, a2, z0);
            z0 = ffma2(v1.y, a3, z0);
            z1 = ffma2(v0.x, b0, z1);
            z1 = ffma2(v0.y, b1, z1);
            z1 = ffma2(v1.x, b2, z1);
            z1 = ffma2(v1.y, b3, z1);
            z[0][p] = z0; z[1][p] = z1;
        }
        wa0 = wa1; wa1 = na;
        wb0 = wb1; wb1 = nb;
    }
}

extern __shared__ float2 smem2[];

__global__ void __launch_bounds__(NT, 1)
lstm_persistent(const float* __restrict__ x,
                const float* __restrict__ b0,
                const float* __restrict__ b1,
                const float* __restrict__ Wfc,
                const float* __restrict__ bfc,
                float* __restrict__ out) {
    // SMEM layout (float2 units); every array 16B-aligned
    float2* h0p = smem2;                 // P_*H_
    float2* c0p = h0p + P_ * H_;         // P_*H_
    float2* h1p = c0p + P_ * H_;         // P_*H_
    float2* c1p = h1p + P_ * H_;         // P_*H_
    float2* zb  = c1p + P_ * H_;         // G_*PST
    float2* xp  = zb + G_ * PST;         // P_*F_
    ull* zbu = (ull*)zb;

    const int tid = threadIdx.x;
    const int g0 = tid;                  // this thread's gates: g0, g0+256
    const int b_base = blockIdx.x * BT;
    const int nb = min(BT, B_ - b_base);

    for (int i = tid; i < 4 * P_ * H_; i += NT)
        smem2[i] = make_float2(0.0f, 0.0f);

    const ull bias0a = pack2(b0[g0], b0[g0]);
    const ull bias0b = pack2(b0[g0 + 256], b0[g0 + 256]);
    const ull bias1a = pack2(b1[g0], b1[g0]);
    const ull bias1b = pack2(b1[g0 + 256], b1[g0 + 256]);
    __syncthreads();

    for (int t = 0; t < T_; ++t) {
        // stage x_t, pair-interleaved: xp[p*F + f] = {x[2p][f], x[2p+1][f]}
        for (int i = tid; i < BT * F_; i += NT) {
            int b = i / F_, f = i % F_;
            float v = (b < nb)
                ? x[((size_t)(b_base + b) * T_ + t) * F_ + f]
                : 0.0f;
            ((float*)xp)[(b >> 1) * F_ * 2 + f * 2 + (b & 1)] = v;
        }
        __syncthreads();

        // ---------- layer 0 ----------
        ull z[2][P_];
#pragma unroll
        for (int p = 0; p < P_; ++p) { z[0][p] = bias0a; z[1][p] = bias0b; }
        gemm2<F_>(g_Wih0T4, xp, z, g0);
        gemm2<H_>(g_Whh0T4, h0p, z, g0);
#pragma unroll
        for (int p = 0; p < P_; ++p) {
            zbu[g0 * PST + p] = z[0][p];
            zbu[(g0 + 256) * PST + p] = z[1][p];
        }
        __syncthreads();

        for (int i = tid; i < P_ * H_; i += NT) {
            int p = i >> 7, j = i & (H_ - 1);
            float2 zi = zb[(j      ) * PST + p];
            float2 zf = zb[(j + 128) * PST + p];
            float2 zg = zb[(j + 256) * PST + p];
            float2 zo = zb[(j + 384) * PST + p];
            float2 c = c0p[p * H_ + j];
            float2 nc, nh;
            nc.x = sigm(zf.x) * c.x + sigm(zi.x) * tanh_f(zg.x);
            nc.y = sigm(zf.y) * c.y + sigm(zi.y) * tanh_f(zg.y);
            nh.x = sigm(zo.x) * tanh_f(nc.x);
            nh.y = sigm(zo.y) * tanh_f(nc.y);
            c0p[p * H_ + j] = nc;
            h0p[p * H_ + j] = nh;
        }
        __syncthreads();

        // ---------- layer 1 ----------
#pragma unroll
        for (int p = 0; p < P_; ++p) { z[0][p] = bias1a; z[1][p] = bias1b; }
        gemm2<H_>(g_Wih1T4, h0p, z, g0);
        gemm2<H_>(g_Whh1T4, h1p, z, g0);
#pragma unroll
        for (int p = 0; p < P_; ++p) {
            zbu[g0 * PST + p] = z[0][p];
            zbu[(g0 + 256) * PST + p] = z[1][p];
        }
        __syncthreads();

        for (int i = tid; i < P_ * H_; i += NT) {
            int p = i >> 7, j = i & (H_ - 1);
            float2 zi = zb[(j      ) * PST + p];
            float2 zf = zb[(j + 128) * PST + p];
            float2 zg = zb[(j + 256) * PST + p];
            float2 zo = zb[(j + 384) * PST + p];
            float2 c = c1p[p * H_ + j];
            float2 nc, nh;
            nc.x = sigm(zf.x) * c.x + sigm(zi.x) * tanh_f(zg.x);
            nc.y = sigm(zf.y) * c.y + sigm(zi.y) * tanh_f(zg.y);
            nh.x = sigm(zo.x) * tanh_f(nc.x);
            nh.y = sigm(zo.y) * tanh_f(nc.y);
            c1p[p * H_ + j] = nc;
            h1p[p * H_ + j] = nh;
        }
        __syncthreads();
    }

    // FC head: out[b] = h1_last[b] . Wfc + bfc
    if (tid < nb) {
        float s = bfc[0];
#pragma unroll
        for (int k = 0; k < H_; ++k) {
            float2 hv = h1p[(tid >> 1) * H_ + k];
            float h = (tid & 1) ? hv.y : hv.x;
            s = fmaf(h, Wfc[k], s);
        }
        out[b_base + tid] = s;
    }
}

extern "C" void kernel_launch(void* const* d_in, const int* in_sizes, int n_in,
                              void* d_out, int out_size) {
    const float* x    = (const float*)d_in[0];
    const float* Wih0 = (const float*)d_in[1];
    const float* Whh0 = (const float*)d_in[2];
    const float* b0   = (const float*)d_in[3];
    const float* Wih1 = (const float*)d_in[4];
    const float* Whh1 = (const float*)d_in[5];
    const float* b1   = (const float*)d_in[6];
    const float* Wfc  = (const float*)d_in[7];
    const float* bfc  = (const float*)d_in[8];
    float* out = (float*)d_out;
    (void)in_sizes; (void)n_in; (void)out_size;

    prep<<<(G_ * (H_ / 4) + 255) / 256, 256>>>(Wih0, Whh0, Wih1, Whh1);

    const int smem_bytes = (4 * P_ * H_ + G_ * PST + P_ * F_) * sizeof(float2);
    cudaFuncSetAttribute(lstm_persistent,
                         cudaFuncAttributeMaxDynamicSharedMemorySize,
                         smem_bytes);

    lstm_persistent<<<(B_ + BT - 1) / BT, NT, smem_bytes>>>(
        x, b0, b1, Wfc, bfc, out);
}

// round 5
// speedup vs baseline: 2.5789x; 1.0476x over previous
#include <cuda_runtime.h>
#include <math.h>

// Problem constants
#define B_  2048
#define T_  512
#define F_  32
#define H_  128
#define G_  512      // 4*H
#define BT  14       // batch rows per CTA -> 147 CTAs = one wave on 148 SMs
#define P_  7        // batch-row pairs per CTA
#define NT  512      // two halves of 256 threads; each thread: gates (t&255, +256)
#define PST 9        // zbuf pair stride in ull
#define CWR 11       // Whh0 k-rows cached in SMEM (of 32)

typedef unsigned long long ull;

// Weights as [kg][gate] float4: coalesced LDG.128 per gate per k-group.
// Padded +2 kg rows for the distance-2 prefetch.
__device__ float4 g_Wih0T4[(F_ / 4 + 2) * G_];
__device__ float4 g_Whh0T4[(H_ / 4 + 2) * G_];
__device__ float4 g_Wih1T4[(H_ / 4 + 2) * G_];
__device__ float4 g_Whh1T4[(H_ / 4 + 2) * G_];

__global__ void prep(const float* __restrict__ Wih0,
                     const float* __restrict__ Whh0,
                     const float* __restrict__ Wih1,
                     const float* __restrict__ Whh1) {
    int idx = blockIdx.x * blockDim.x + threadIdx.x;  // 0 .. 512*32-1
    int g = idx >> 5, kg = idx & 31;
    if (kg < F_ / 4)
        g_Wih0T4[kg * G_ + g] = *(const float4*)(Wih0 + g * F_ + 4 * kg);
    g_Whh0T4[kg * G_ + g] = *(const float4*)(Whh0 + g * H_ + 4 * kg);
    g_Wih1T4[kg * G_ + g] = *(const float4*)(Wih1 + g * H_ + 4 * kg);
    g_Whh1T4[kg * G_ + g] = *(const float4*)(Whh1 + g * H_ + 4 * kg);
}

__device__ __forceinline__ ull ffma2(ull a, ull b, ull c) {
    ull d;
    asm("fma.rn.f32x2 %0, %1, %2, %3;" : "=l"(d) : "l"(a), "l"(b), "l"(c));
    return d;
}
__device__ __forceinline__ ull dup2(float w) {
    ull d;
    asm("mov.b64 %0, {%1, %1};" : "=l"(d) : "f"(w));
    return d;
}
__device__ __forceinline__ ull pack2(float lo, float hi) {
    return (ull)__float_as_uint(lo) | ((ull)__float_as_uint(hi) << 32);
}
__device__ __forceinline__ float sigm(float x) {
    return 1.0f / (1.0f + __expf(-x));
}
__device__ __forceinline__ float tanh_f(float x) {
    float e = __expf(-2.0f * fabsf(x));
    float t = (1.0f - e) / (1.0f + e);
    return x >= 0.0f ? t : -t;
}

// Inner k-group body: z[q][p] += hpair[p][4kg..4kg+3] * w{a,b}
template <int KDIM, int NP>
__device__ __forceinline__ void kbody(float4 wa, float4 wb,
                                      const float2* __restrict__ hp,
                                      ull z[2][NP], int kidx) {
    ull a0 = dup2(wa.x), a1 = dup2(wa.y), a2 = dup2(wa.z), a3 = dup2(wa.w);
    ull b0 = dup2(wb.x), b1 = dup2(wb.y), b2 = dup2(wb.z), b3 = dup2(wb.w);
#pragma unroll
    for (int p = 0; p < NP; ++p) {
        const ulonglong2* hv = (const ulonglong2*)(hp + p * KDIM) + 2 * kidx;
        ulonglong2 v0 = hv[0];
        ulonglong2 v1 = hv[1];
        ull z0 = z[0][p], z1 = z[1][p];
        z0 = ffma2(v0.x, a0, z0);
        z0 = ffma2(v0.y, a1, z0);
        z0 = ffma2(v1.x, a2, z0);
        z0 = ffma2(v1.y, a3, z0);
        z1 = ffma2(v0.x, b0, z1);
        z1 = ffma2(v0.y, b1, z1);
        z1 = ffma2(v1.x, b2, z1);
        z1 = ffma2(v1.y, b3, z1);
        z[0][p] = z0; z[1][p] = z1;
    }
}

// GEMM panel, weights streamed from global with distance-2 prefetch.
// hp points at this half's first pair row; kbase offsets the k index.
template <int KDIM, int KG, int NP>
__device__ __forceinline__ void gemm_g(const float4* __restrict__ W4,
                                       const float2* __restrict__ hp,
                                       int kbase, ull z[2][NP], int g0) {
    const float4* pA = W4 + g0;
    const float4* pB = W4 + g0 + 256;
    float4 wa0 = pA[0], wa1 = pA[G_];
    float4 wb0 = pB[0], wb1 = pB[G_];
#pragma unroll 1
    for (int kg = 0; kg < KG; ++kg) {
        float4 na = pA[(size_t)(kg + 2) * G_];
        float4 nb = pB[(size_t)(kg + 2) * G_];
        kbody<KDIM, NP>(wa0, wb0, hp, z, kbase + kg);
        wa0 = wa1; wa1 = na;
        wb0 = wb1; wb1 = nb;
    }
}

// GEMM panel, weights from SMEM cache (no prefetch needed).
template <int KDIM, int KG, int NP>
__device__ __forceinline__ void gemm_s(const float4* __restrict__ Ws,
                                       const float2* __restrict__ hp,
                                       int kbase, ull z[2][NP], int g0) {
#pragma unroll 1
    for (int kg = 0; kg < KG; ++kg) {
        float4 wa = Ws[kg * G_ + g0];
        float4 wb = Ws[kg * G_ + g0 + 256];
        kbody<KDIM, NP>(wa, wb, hp, z, kbase + kg);
    }
}

extern __shared__ float4 smem4[];

template <int NP>
__device__ __forceinline__ void step_layer(const float4* sWih, int sWihKG,
                                           const float4* sWhh_s, int sWhhKGs,
                                           const float4* gWhh, int gWhhKG,
                                           const float2* xin, int xKD,
                                           const float2* hin,
                                           ull biasA, ull biasB,
                                           ull* zbu, int g0) {
    ull z[2][NP];
#pragma unroll
    for (int p = 0; p < NP; ++p) { z[0][p] = biasA; z[1][p] = biasB; }
    (void)sWihKG;
    if (xKD == F_) gemm_s<F_, F_ / 4, NP>(sWih, xin, 0, z, g0);
    else           gemm_g<H_, H_ / 4, NP>(sWih, xin, 0, z, g0);
    gemm_s<H_, CWR, NP>(sWhh_s, hin, 0, z, g0);
    (void)sWhhKGs; (void)gWhhKG;
    gemm_g<H_, H_ / 4 - CWR, NP>(gWhh, hin, CWR, z, g0);
#pragma unroll
    for (int p = 0; p < NP; ++p) {
        zbu[g0 * PST + p] = z[0][p];
        zbu[(g0 + 256) * PST + p] = z[1][p];
    }
}

__global__ void __launch_bounds__(NT, 1)
lstm_persistent(const float* __restrict__ x,
                const float* __restrict__ b0,
                const float* __restrict__ b1,
                const float* __restrict__ Wfc,
                const float* __restrict__ bfc,
                float* __restrict__ out) {
    // SMEM: [Wih0 cache 8 rows][Whh0 cache CWR rows][h0,c0,h1,c1][zbuf][xp]
    float4* sWih0 = smem4;                            // 8*G_ float4
    float4* sWhh0 = smem4 + (F_ / 4) * G_;            // CWR*G_ float4
    float2* hbase = (float2*)(smem4 + (F_ / 4 + CWR) * G_);
    float2* h0p = hbase;                 // P_*H_
    float2* c0p = h0p + P_ * H_;
    float2* h1p = c0p + P_ * H_;
    float2* c1p = h1p + P_ * H_;
    ull* zbu = (ull*)(c1p + P_ * H_);    // G_*PST
    float2* xp = (float2*)(zbu + G_ * PST);  // P_*F_
    float2* zb = (float2*)zbu;

    const int tid = threadIdx.x;
    const int g0 = tid & 255;            // gates g0 and g0+256
    const int half = tid >> 8;           // 0: pairs 0-3, 1: pairs 4-6
    const int b_base = blockIdx.x * BT;
    const int nb = min(BT, B_ - b_base);

    // fill weight caches (once per launch)
    for (int i = tid; i < (F_ / 4) * G_; i += NT) sWih0[i] = g_Wih0T4[i];
    for (int i = tid; i < CWR * G_; i += NT) sWhh0[i] = g_Whh0T4[i];
    // zero h/c
    for (int i = tid; i < 4 * P_ * H_; i += NT) hbase[i] = make_float2(0.f, 0.f);

    const ull bias0a = pack2(b0[g0], b0[g0]);
    const ull bias0b = pack2(b0[g0 + 256], b0[g0 + 256]);
    const ull bias1a = pack2(b1[g0], b1[g0]);
    const ull bias1b = pack2(b1[g0 + 256], b1[g0 + 256]);
    __syncthreads();

    for (int t = 0; t < T_; ++t) {
        // stage x_t pair-interleaved
        for (int i = tid; i < BT * F_; i += NT) {
            int b = i / F_, f = i % F_;
            float v = (b < nb)
                ? x[((size_t)(b_base + b) * T_ + t) * F_ + f]
                : 0.0f;
            ((float*)xp)[(b >> 1) * F_ * 2 + f * 2 + (b & 1)] = v;
        }
        __syncthreads();

        // ---------- layer 0 ----------
        if (half == 0)
            step_layer<4>(sWih0, F_ / 4, sWhh0, CWR, g_Whh0T4 + CWR * G_,
                          H_ / 4 - CWR, xp, F_, h0p, bias0a, bias0b, zbu, g0);
        else
            step_layer<3>(sWih0, F_ / 4, sWhh0, CWR, g_Whh0T4 + CWR * G_,
                          H_ / 4 - CWR, xp + 4 * F_, F_, h0p + 4 * H_,
                          bias0a, bias0b, zbu + 4, g0);
        __syncthreads();

        for (int i = tid; i < P_ * H_; i += NT) {
            int p = i >> 7, j = i & (H_ - 1);
            float2 zi = zb[(j      ) * PST + p];
            float2 zf = zb[(j + 128) * PST + p];
            float2 zg = zb[(j + 256) * PST + p];
            float2 zo = zb[(j + 384) * PST + p];
            float2 c = c0p[p * H_ + j];
            float2 nc, nh;
            nc.x = sigm(zf.x) * c.x + sigm(zi.x) * tanh_f(zg.x);
            nc.y = sigm(zf.y) * c.y + sigm(zi.y) * tanh_f(zg.y);
            nh.x = sigm(zo.x) * tanh_f(nc.x);
            nh.y = sigm(zo.y) * tanh_f(nc.y);
            c0p[p * H_ + j] = nc;
            h0p[p * H_ + j] = nh;
        }
        __syncthreads();

        // ---------- layer 1 ----------
        {
            ull z[2][4];
            if (half == 0) {
#pragma unroll
                for (int p = 0; p < 4; ++p) { z[0][p] = bias1a; z[1][p] = bias1b; }
                ull (*zz)[4] = z;
                gemm_g<H_, H_ / 4, 4>(g_Wih1T4, h0p, 0, zz, g0);
                gemm_g<H_, H_ / 4, 4>(g_Whh1T4, h1p, 0, zz, g0);
#pragma unroll
                for (int p = 0; p < 4; ++p) {
                    zbu[g0 * PST + p] = z[0][p];
                    zbu[(g0 + 256) * PST + p] = z[1][p];
                }
            } else {
                ull z3[2][3];
#pragma unroll
                for (int p = 0; p < 3; ++p) { z3[0][p] = bias1a; z3[1][p] = bias1b; }
                gemm_g<H_, H_ / 4, 3>(g_Wih1T4, h0p + 4 * H_, 0, z3, g0);
                gemm_g<H_, H_ / 4, 3>(g_Whh1T4, h1p + 4 * H_, 0, z3, g0);
#pragma unroll
                for (int p = 0; p < 3; ++p) {
                    zbu[g0 * PST + 4 + p] = z3[0][p];
                    zbu[(g0 + 256) * PST + 4 + p] = z3[1][p];
                }
            }
        }
        __syncthreads();

        for (int i = tid; i < P_ * H_; i += NT) {
            int p = i >> 7, j = i & (H_ - 1);
            float2 zi = zb[(j      ) * PST + p];
            float2 zf = zb[(j + 128) * PST + p];
            float2 zg = zb[(j + 256) * PST + p];
            float2 zo = zb[(j + 384) * PST + p];
            float2 c = c1p[p * H_ + j];
            float2 nc, nh;
            nc.x = sigm(zf.x) * c.x + sigm(zi.x) * tanh_f(zg.x);
            nc.y = sigm(zf.y) * c.y + sigm(zi.y) * tanh_f(zg.y);
            nh.x = sigm(zo.x) * tanh_f(nc.x);
            nh.y = sigm(zo.y) * tanh_f(nc.y);
            c1p[p * H_ + j] = nc;
            h1p[p * H_ + j] = nh;
        }
        __syncthreads();
    }

    // FC head
    if (tid < nb) {
        float s = bfc[0];
#pragma unroll
        for (int k = 0; k < H_; ++k) {
            float2 hv = h1p[(tid >> 1) * H_ + k];
            float h = (tid & 1) ? hv.y : hv.x;
            s = fmaf(h, Wfc[k], s);
        }
        out[b_base + tid] = s;
    }
}

extern "C" void kernel_launch(void* const* d_in, const int* in_sizes, int n_in,
                              void* d_out, int out_size) {
    const float* x    = (const float*)d_in[0];
    const float* Wih0 = (const float*)d_in[1];
    const float* Whh0 = (const float*)d_in[2];
    const float* b0   = (const float*)d_in[3];
    const float* Wih1 = (const float*)d_in[4];
    const float* Whh1 = (const float*)d_in[5];
    const float* b1   = (const float*)d_in[6];
    const float* Wfc  = (const float*)d_in[7];
    const float* bfc  = (const float*)d_in[8];
    float* out = (float*)d_out;
    (void)in_sizes; (void)n_in; (void)out_size;

    prep<<<(G_ * (H_ / 4) + 255) / 256, 256>>>(Wih0, Whh0, Wih1, Whh1);

    const int smem_bytes =
        (F_ / 4 + CWR) * G_ * (int)sizeof(float4) +          // weight caches
        4 * P_ * H_ * (int)sizeof(float2) +                   // h/c
        G_ * PST * (int)sizeof(ull) +                         // zbuf
        P_ * F_ * (int)sizeof(float2);                        // xp
    cudaFuncSetAttribute(lstm_persistent,
                         cudaFuncAttributeMaxDynamicSharedMemorySize,
                         smem_bytes);

    lstm_persistent<<<(B_ + BT - 1) / BT, NT, smem_bytes>>>(
        x, b0, b1, Wfc, bfc, out);
}